// round 17
// baseline (speedup 1.0000x reference)
#include <cuda_runtime.h>
#include <cuda_bf16.h>
#include <math.h>

#define N_NODES_MAX 100000
#define N_EDGES_MAX 1600000
#define DIM 128
#define NCLS 40
#define SCB 1024  // elements per scan block (4 per thread)

// ---------------- bf16 split helpers ----------------------------------------
__device__ __forceinline__ unsigned pack_bf2(__nv_bfloat16 a, __nv_bfloat16 b) {
    __nv_bfloat162 t;
    t.x = a; t.y = b;
    return *reinterpret_cast<unsigned*>(&t);
}
__device__ __forceinline__ void split_bf(float f, __nv_bfloat16& hi, __nv_bfloat16& lo) {
    hi = __float2bfloat16_rn(f);
    lo = __float2bfloat16_rn(f - __bfloat162float(hi));
}
__device__ __forceinline__ void mma_bf16(float* c, unsigned a0, unsigned a1,
                                         unsigned a2, unsigned a3,
                                         unsigned b0, unsigned b1) {
    asm volatile(
        "mma.sync.aligned.m16n8k16.row.col.f32.bf16.bf16.f32 "
        "{%0,%1,%2,%3}, {%4,%5,%6,%7}, {%8,%9}, {%0,%1,%2,%3};"
        : "+f"(c[0]), "+f"(c[1]), "+f"(c[2]), "+f"(c[3])
        : "r"(a0), "r"(a1), "r"(a2), "r"(a3), "r"(b0), "r"(b1));
}

// ---------------- scratch (static device allocations; no cudaMalloc) -------
__device__ int g_deg[N_NODES_MAX];
__device__ int g_offs[N_NODES_MAX + 1];
__device__ int g_cur[N_NODES_MAX];
__device__ int g_csr[N_EDGES_MAX];
__device__ int g_bsum[128];
__device__ int g_bflag[128];
__device__ __align__(16) float g_agg[(size_t)N_NODES_MAX * DIM];
__device__ __align__(16) float g_y1[(size_t)N_NODES_MAX * NCLS];
// pre-converted weights: packed bf16 (hi,lo) pairs in n-major [n][kpair] layout
__device__ unsigned g_wth1a[128 * 64];
__device__ unsigned g_wtl1a[128 * 64];
__device__ unsigned g_wth1b[128 * 64];
__device__ unsigned g_wtl1b[128 * 64];
__device__ unsigned g_wth2a[40 * 64];
__device__ unsigned g_wtl2a[40 * 64];

// ---------------- weight pre-conversion (runs once) -------------------------
__global__ void convert_weights_kernel(const float* __restrict__ W1a,
                                       const float* __restrict__ W1b,
                                       const float* __restrict__ W2a) {
    int i = blockIdx.x * blockDim.x + threadIdx.x;
    if (i < 8192) {
        int kp = i >> 7, nn = i & 127;
        __nv_bfloat16 h0, l0, h1, l1;
        float f0 = W1a[(2 * kp) * 128 + nn];
        float f1 = W1a[(2 * kp + 1) * 128 + nn];
        split_bf(f0, h0, l0); split_bf(f1, h1, l1);
        g_wth1a[nn * 64 + kp] = pack_bf2(h0, h1);
        g_wtl1a[nn * 64 + kp] = pack_bf2(l0, l1);
        f0 = W1b[(2 * kp) * 128 + nn];
        f1 = W1b[(2 * kp + 1) * 128 + nn];
        split_bf(f0, h0, l0); split_bf(f1, h1, l1);
        g_wth1b[nn * 64 + kp] = pack_bf2(h0, h1);
        g_wtl1b[nn * 64 + kp] = pack_bf2(l0, l1);
    }
    if (i < 2560) {
        int kp = i / 40, nn = i - kp * 40;
        __nv_bfloat16 h0, l0, h1, l1;
        float f0 = W2a[(2 * kp) * 40 + nn];
        float f1 = W2a[(2 * kp + 1) * 40 + nn];
        split_bf(f0, h0, l0); split_bf(f1, h1, l1);
        g_wth2a[nn * 64 + kp] = pack_bf2(h0, h1);
        g_wtl2a[nn * 64 + kp] = pack_bf2(l0, l1);
    }
}

// ---------------- CSR build -------------------------------------------------
// hist: 4 independent int4 loads per thread (8 edges); also resets scan flags.
__global__ __launch_bounds__(256) void hist_kernel(const int4* __restrict__ e4, int m4,
                                                   const int2* __restrict__ e, int m) {
    if (blockIdx.x == 0 && threadIdx.x < 128) g_bflag[threadIdx.x] = 0;
    int i = blockIdx.x * blockDim.x + threadIdx.x;
    int gs = gridDim.x * blockDim.x;
    int j0 = i, j1 = i + gs, j2 = i + 2 * gs, j3 = i + 3 * gs;
    int4 p0, p1, p2, p3;
    bool v0 = j0 < m4, v1 = j1 < m4, v2 = j2 < m4, v3 = j3 < m4;
    if (v0) p0 = e4[j0];
    if (v1) p1 = e4[j1];
    if (v2) p2 = e4[j2];
    if (v3) p3 = e4[j3];
    if (v0) { atomicAdd(&g_deg[p0.y], 1); atomicAdd(&g_deg[p0.w], 1); }
    if (v1) { atomicAdd(&g_deg[p1.y], 1); atomicAdd(&g_deg[p1.w], 1); }
    if (v2) { atomicAdd(&g_deg[p2.y], 1); atomicAdd(&g_deg[p2.w], 1); }
    if (v3) { atomicAdd(&g_deg[p3.y], 1); atomicAdd(&g_deg[p3.w], 1); }
    if (i == 0 && (m & 1)) atomicAdd(&g_deg[e[m - 1].y], 1);
}

// single-pass scan: per-block scan + decoupled publish/lookback of block sums.
// All nb (<=128) blocks fit in one wave (98 blocks, 148 SMs) -> no deadlock.
__global__ __launch_bounds__(256) void scan_kernel(int n, int nb) {
    __shared__ int s[SCB];
    __shared__ int ws[8];
    __shared__ int pre[128];
    __shared__ int boff_s;
    int b = blockIdx.x;
    int base = b * SCB;
    int tid = threadIdx.x;
    for (int j = tid; j < SCB; j += 256)
        s[j] = (base + j < n) ? g_deg[base + j] : 0;
    __syncthreads();
    int mysum = 0;
#pragma unroll
    for (int j = 0; j < 4; j++) mysum += s[tid * 4 + j];
    int lane = tid & 31, wid = tid >> 5;
    int v = mysum;
#pragma unroll
    for (int o = 1; o < 32; o <<= 1) {
        int u = __shfl_up_sync(0xffffffffu, v, o);
        if (lane >= o) v += u;
    }
    if (lane == 31) ws[wid] = v;
    __syncthreads();
    if (wid == 0 && lane < 8) {
        int w = ws[lane];
#pragma unroll
        for (int o = 1; o < 8; o <<= 1) {
            int u = __shfl_up_sync(0xffu, w, o);
            if (lane >= o) w += u;
        }
        ws[lane] = w;
    }
    __syncthreads();
    int block_total = ws[7];
    // publish this block's total ASAP
    if (tid == 0) {
        g_bsum[b] = block_total;
        __threadfence();
        atomicExch(&g_bflag[b], 1);
    }
    // lookback: wait for all predecessors (parallel, one thread each)
    if (tid < b) {
        while (atomicAdd(&g_bflag[tid], 0) == 0) {}
        pre[tid] = g_bsum[tid];
    }
    __syncthreads();
    if (tid == 0) {
        int acc = 0;
        for (int t = 0; t < b; t++) acc += pre[t];
        boff_s = acc;
        if (b == nb - 1) g_offs[n] = acc + block_total;
    }
    __syncthreads();
    int run = (v - mysum) + ((wid > 0) ? ws[wid - 1] : 0) + boff_s;
#pragma unroll
    for (int j = 0; j < 4; j++) {
        int idx = tid * 4 + j;
        int t = s[idx];
        s[idx] = run;
        run += t;
    }
    __syncthreads();
    for (int j = tid; j < SCB; j += 256) {
        int gi = base + j;
        if (gi < n) { g_offs[gi] = s[j]; g_cur[gi] = s[j]; }
    }
}

// fill: 4 independent (load -> 2 atomic -> 2 store) chains per thread
__global__ __launch_bounds__(256) void fill_kernel(const int4* __restrict__ e4, int m4,
                                                   const int2* __restrict__ e, int m) {
    int i = blockIdx.x * blockDim.x + threadIdx.x;
    int gs = gridDim.x * blockDim.x;
    int j0 = i, j1 = i + gs, j2 = i + 2 * gs, j3 = i + 3 * gs;
    int4 p0, p1, p2, p3;
    bool v0 = j0 < m4, v1 = j1 < m4, v2 = j2 < m4, v3 = j3 < m4;
    if (v0) p0 = e4[j0];
    if (v1) p1 = e4[j1];
    if (v2) p2 = e4[j2];
    if (v3) p3 = e4[j3];
    int q0a = 0, q0b = 0, q1a = 0, q1b = 0, q2a = 0, q2b = 0, q3a = 0, q3b = 0;
    if (v0) { q0a = atomicAdd(&g_cur[p0.y], 1); q0b = atomicAdd(&g_cur[p0.w], 1); }
    if (v1) { q1a = atomicAdd(&g_cur[p1.y], 1); q1b = atomicAdd(&g_cur[p1.w], 1); }
    if (v2) { q2a = atomicAdd(&g_cur[p2.y], 1); q2b = atomicAdd(&g_cur[p2.w], 1); }
    if (v3) { q3a = atomicAdd(&g_cur[p3.y], 1); q3b = atomicAdd(&g_cur[p3.w], 1); }
    if (v0) { g_csr[q0a] = p0.x; g_csr[q0b] = p0.z; }
    if (v1) { g_csr[q1a] = p1.x; g_csr[q1b] = p1.z; }
    if (v2) { g_csr[q2a] = p2.x; g_csr[q2b] = p2.z; }
    if (v3) { g_csr[q3a] = p3.x; g_csr[q3b] = p3.z; }
    if (i == 0 && (m & 1)) {
        int2 ed = e[m - 1];
        int p = atomicAdd(&g_cur[ed.y], 1);
        g_csr[p] = ed.x;
    }
}

// ---------------- agg1: warp per node, 4-way pipelined 128-dim gather -------
__global__ __launch_bounds__(256) void agg_kernel(const float4* __restrict__ x4, int n) {
    int gt = blockIdx.x * blockDim.x + threadIdx.x;
    int w = gt >> 5;
    int lane = gt & 31;
    if (w >= n) return;
    float4* o4 = (float4*)g_agg;
    float4 a0 = x4[(size_t)w * 32 + lane];  // self term
    float4 a1 = make_float4(0.f, 0.f, 0.f, 0.f);
    float4 a2 = make_float4(0.f, 0.f, 0.f, 0.f);
    float4 a3 = make_float4(0.f, 0.f, 0.f, 0.f);
    int j = g_offs[w], e = g_offs[w + 1];
    for (; j + 4 <= e; j += 4) {
        int s0 = g_csr[j + 0];
        int s1 = g_csr[j + 1];
        int s2 = g_csr[j + 2];
        int s3 = g_csr[j + 3];
        float4 v0 = __ldg(&x4[(size_t)s0 * 32 + lane]);
        float4 v1 = __ldg(&x4[(size_t)s1 * 32 + lane]);
        float4 v2 = __ldg(&x4[(size_t)s2 * 32 + lane]);
        float4 v3 = __ldg(&x4[(size_t)s3 * 32 + lane]);
        a0.x += v0.x; a0.y += v0.y; a0.z += v0.z; a0.w += v0.w;
        a1.x += v1.x; a1.y += v1.y; a1.z += v1.z; a1.w += v1.w;
        a2.x += v2.x; a2.y += v2.y; a2.z += v2.z; a2.w += v2.w;
        a3.x += v3.x; a3.y += v3.y; a3.z += v3.z; a3.w += v3.w;
    }
    for (; j < e; j++) {
        int s = g_csr[j];
        float4 v = __ldg(&x4[(size_t)s * 32 + lane]);
        a0.x += v.x; a0.y += v.y; a0.z += v.z; a0.w += v.w;
    }
    a0.x += a1.x + a2.x + a3.x;
    a0.y += a1.y + a2.y + a3.y;
    a0.z += a1.z + a2.z + a3.z;
    a0.w += a1.w + a2.w + a3.w;
    o4[(size_t)w * 32 + lane] = a0;
}

// ---------------- layer 1 + y1 projection via split-bf16 MMA ----------------
#define SAW 68
#define OFF_A2H 0
#define OFF_A2L (OFF_A2H + 64 * SAW)
#define OFF_WTH (OFF_A2L + 64 * SAW)
#define OFF_WTL (OFF_WTH + 128 * SAW)
#define OFF_BSA (OFF_WTL + 128 * SAW)
#define OFF_BSB (OFF_BSA + 128)
#define G1_SMEM_WORDS (OFF_BSB + 128)
#define G1_SMEM_BYTES (G1_SMEM_WORDS * 4)

__device__ __forceinline__ void g1_load_W128(unsigned* WTH, unsigned* WTL,
                                             const unsigned* __restrict__ GH,
                                             const unsigned* __restrict__ GL, int tid) {
    for (int i = tid; i < 8192; i += 256) {
        int kp = i & 63, nn = i >> 6;
        WTH[nn * SAW + kp] = GH[i];
        WTL[nn * SAW + kp] = GL[i];
    }
}

__global__ __launch_bounds__(256) void gemm1_kernel(
    const float* __restrict__ b1a, const float* __restrict__ b1b, int n) {
    extern __shared__ unsigned su[];
    unsigned* A2H = su + OFF_A2H;
    unsigned* A2L = su + OFF_A2L;
    unsigned* WTH = su + OFF_WTH;
    unsigned* WTL = su + OFF_WTL;
    float* bsA = (float*)(su + OFF_BSA);
    float* bsB = (float*)(su + OFF_BSB);

    int tid = threadIdx.x;
    int lane = tid & 31, wid = tid >> 5;
    int r0 = (wid >> 1) << 4;   // warp row base (0,16,32,48)
    int n0 = (wid & 1) << 6;    // warp col base (0,64)
    int row0 = blockIdx.x * 64;

    for (int i = tid; i < 64 * 32; i += 256) {
        int r = i >> 5, c = i & 31;
        float4 v = (row0 + r < n) ? ((const float4*)g_agg)[(size_t)(row0 + r) * 32 + c]
                                  : make_float4(0.f, 0.f, 0.f, 0.f);
        __nv_bfloat16 hx, lx, hy, ly, hz, lz, hw, lw;
        split_bf(v.x, hx, lx); split_bf(v.y, hy, ly);
        split_bf(v.z, hz, lz); split_bf(v.w, hw, lw);
        A2H[r * SAW + 2 * c + 0] = pack_bf2(hx, hy);
        A2H[r * SAW + 2 * c + 1] = pack_bf2(hz, hw);
        A2L[r * SAW + 2 * c + 0] = pack_bf2(lx, ly);
        A2L[r * SAW + 2 * c + 1] = pack_bf2(lz, lw);
    }
    g1_load_W128(WTH, WTL, g_wth1a, g_wtl1a, tid);
    if (tid < 128) { bsA[tid] = b1a[tid]; bsB[tid] = b1b[tid]; }
    __syncthreads();

    float acc[8][4];
#pragma unroll
    for (int t = 0; t < 8; t++)
#pragma unroll
        for (int q = 0; q < 4; q++) acc[t][q] = 0.f;

    int arow = (r0 + (lane >> 2)) * SAW + (lane & 3);
    // ---------------- phase 1 mma ----------------
    for (int kk = 0; kk < 8; kk++) {
        int aw = arow + kk * 8;
        unsigned ah0 = A2H[aw], ah1 = A2H[aw + 8 * SAW];
        unsigned ah2 = A2H[aw + 4], ah3 = A2H[aw + 8 * SAW + 4];
        unsigned al0 = A2L[aw], al1 = A2L[aw + 8 * SAW];
        unsigned al2 = A2L[aw + 4], al3 = A2L[aw + 8 * SAW + 4];
#pragma unroll
        for (int t = 0; t < 8; t++) {
            int bw = (n0 + t * 8 + (lane >> 2)) * SAW + kk * 8 + (lane & 3);
            unsigned bh0 = WTH[bw], bh1 = WTH[bw + 4];
            unsigned bl0 = WTL[bw], bl1 = WTL[bw + 4];
            mma_bf16(acc[t], ah0, ah1, ah2, ah3, bh0, bh1);
            mma_bf16(acc[t], ah0, ah1, ah2, ah3, bl0, bl1);
            mma_bf16(acc[t], al0, al1, al2, al3, bh0, bh1);
        }
    }
    __syncthreads();

    // epilogue 1: T = relu(acc + b1a) -> A2; load W1b
    {
        int row = r0 + (lane >> 2);
#pragma unroll
        for (int t = 0; t < 8; t++) {
            int col = n0 + t * 8 + (lane & 3) * 2;
            int pair = col >> 1;
            float h00 = fmaxf(acc[t][0] + bsA[col], 0.f);
            float h01 = fmaxf(acc[t][1] + bsA[col + 1], 0.f);
            float h10 = fmaxf(acc[t][2] + bsA[col], 0.f);
            float h11 = fmaxf(acc[t][3] + bsA[col + 1], 0.f);
            __nv_bfloat16 h, l, h2, l2;
            split_bf(h00, h, l); split_bf(h01, h2, l2);
            A2H[row * SAW + pair] = pack_bf2(h, h2);
            A2L[row * SAW + pair] = pack_bf2(l, l2);
            split_bf(h10, h, l); split_bf(h11, h2, l2);
            A2H[(row + 8) * SAW + pair] = pack_bf2(h, h2);
            A2L[(row + 8) * SAW + pair] = pack_bf2(l, l2);
            acc[t][0] = acc[t][1] = acc[t][2] = acc[t][3] = 0.f;
        }
    }
    g1_load_W128(WTH, WTL, g_wth1b, g_wtl1b, tid);
    __syncthreads();

    // ---------------- phase 2 mma ----------------
    for (int kk = 0; kk < 8; kk++) {
        int aw = arow + kk * 8;
        unsigned ah0 = A2H[aw], ah1 = A2H[aw + 8 * SAW];
        unsigned ah2 = A2H[aw + 4], ah3 = A2H[aw + 8 * SAW + 4];
        unsigned al0 = A2L[aw], al1 = A2L[aw + 8 * SAW];
        unsigned al2 = A2L[aw + 4], al3 = A2L[aw + 8 * SAW + 4];
#pragma unroll
        for (int t = 0; t < 8; t++) {
            int bw = (n0 + t * 8 + (lane >> 2)) * SAW + kk * 8 + (lane & 3);
            unsigned bh0 = WTH[bw], bh1 = WTH[bw + 4];
            unsigned bl0 = WTL[bw], bl1 = WTL[bw + 4];
            mma_bf16(acc[t], ah0, ah1, ah2, ah3, bh0, bh1);
            mma_bf16(acc[t], ah0, ah1, ah2, ah3, bl0, bl1);
            mma_bf16(acc[t], al0, al1, al2, al3, bh0, bh1);
        }
    }
    __syncthreads();  // phase-2 reads complete before overwrite

    // epilogue 2: X = relu(acc + b1b) -> A2 (hi/lo); load W2a
    {
        int row = r0 + (lane >> 2);
#pragma unroll
        for (int t = 0; t < 8; t++) {
            int col = n0 + t * 8 + (lane & 3) * 2;
            int pair = col >> 1;
            float h00 = fmaxf(acc[t][0] + bsB[col], 0.f);
            float h01 = fmaxf(acc[t][1] + bsB[col + 1], 0.f);
            float h10 = fmaxf(acc[t][2] + bsB[col], 0.f);
            float h11 = fmaxf(acc[t][3] + bsB[col + 1], 0.f);
            __nv_bfloat16 h, l, h2, l2;
            split_bf(h00, h, l); split_bf(h01, h2, l2);
            A2H[row * SAW + pair] = pack_bf2(h, h2);
            A2L[row * SAW + pair] = pack_bf2(l, l2);
            split_bf(h10, h, l); split_bf(h11, h2, l2);
            A2H[(row + 8) * SAW + pair] = pack_bf2(h, h2);
            A2L[(row + 8) * SAW + pair] = pack_bf2(l, l2);
        }
    }
    for (int i = tid; i < 2560; i += 256) {
        int kp = i & 63, nn = i >> 6;
        WTH[nn * SAW + kp] = g_wth2a[i];
        WTL[nn * SAW + kp] = g_wtl2a[i];
    }
    __syncthreads();

    // ---------------- phase 3 mma: y1 = X @ W2a (warps with wid&1==0) -------
    if ((wid & 1) == 0) {
        float accy[5][4];
#pragma unroll
        for (int t = 0; t < 5; t++)
#pragma unroll
            for (int q = 0; q < 4; q++) accy[t][q] = 0.f;

        for (int kk = 0; kk < 8; kk++) {
            int aw = arow + kk * 8;
            unsigned ah0 = A2H[aw], ah1 = A2H[aw + 8 * SAW];
            unsigned ah2 = A2H[aw + 4], ah3 = A2H[aw + 8 * SAW + 4];
            unsigned al0 = A2L[aw], al1 = A2L[aw + 8 * SAW];
            unsigned al2 = A2L[aw + 4], al3 = A2L[aw + 8 * SAW + 4];
#pragma unroll
            for (int t = 0; t < 5; t++) {
                int bw = (t * 8 + (lane >> 2)) * SAW + kk * 8 + (lane & 3);
                unsigned bh0 = WTH[bw], bh1 = WTH[bw + 4];
                unsigned bl0 = WTL[bw], bl1 = WTL[bw + 4];
                mma_bf16(accy[t], ah0, ah1, ah2, ah3, bh0, bh1);
                mma_bf16(accy[t], ah0, ah1, ah2, ah3, bl0, bl1);
                mma_bf16(accy[t], al0, al1, al2, al3, bh0, bh1);
            }
        }
        int row = row0 + r0 + (lane >> 2);
#pragma unroll
        for (int t = 0; t < 5; t++) {
            int col = t * 8 + (lane & 3) * 2;
            if (row < n) {
                float2 o; o.x = accy[t][0]; o.y = accy[t][1];
                *(float2*)&g_y1[(size_t)row * 40 + col] = o;
            }
            if (row + 8 < n) {
                float2 o; o.x = accy[t][2]; o.y = accy[t][3];
                *(float2*)&g_y1[(size_t)(row + 8) * 40 + col] = o;
            }
        }
    }
}

// ---------------- final: out = softmax(relu(agg(y1) + b2a) @ W2b + b2b) -----
#define G2B_ROWS 128
#define G2B_SMEM_FLOATS (G2B_ROWS * 41 + 40 * 40 + 40 + 40)
__global__ __launch_bounds__(256) void gemm2b_kernel(
    const float* __restrict__ b2a, const float* __restrict__ W2b,
    const float* __restrict__ b2b, float* __restrict__ out, int n) {
    extern __shared__ float sm[];
    float* As = sm;
    float* Wb = sm + G2B_ROWS * 41;
    float* ba = Wb + 40 * 40;
    float* bb = ba + 40;

    int tid = threadIdx.x;
    int lane = tid & 31, wid = tid >> 5;
    int row0 = blockIdx.x * G2B_ROWS;
    const float2* y2 = (const float2*)g_y1;

    // fused aggregation staging: each of 8 warps stages 16 nodes
    for (int i = 0; i < 16; i++) {
        int r = wid * 16 + i;
        int row = row0 + r;
        float2 acc = make_float2(0.f, 0.f);
        if (row < n) {
            int s0 = g_offs[row], s1 = g_offs[row + 1];
            if (lane < 20) {
                acc = y2[(size_t)row * 20 + lane];
                for (int j = s0; j < s1; j++) {
                    int s = g_csr[j];
                    float2 v = __ldg(&y2[(size_t)s * 20 + lane]);
                    acc.x += v.x; acc.y += v.y;
                }
            }
        }
        if (lane < 20) {
            As[r * 41 + 2 * lane + 0] = acc.x;
            As[r * 41 + 2 * lane + 1] = acc.y;
        }
    }
    for (int i = tid; i < 1600; i += 256) Wb[i] = W2b[i];
    if (tid < 40) { ba[tid] = b2a[tid]; bb[tid] = b2b[tid]; }
    __syncthreads();

    // thread-per-row (only first 128 threads own a row)
    if (tid < G2B_ROWS) {
        float h[40];
        const float* arow = &As[tid * 41];
#pragma unroll
        for (int c = 0; c < 40; c++) h[c] = fmaxf(arow[c] + ba[c], 0.f);

        float o[40];
#pragma unroll
        for (int c = 0; c < 40; c++) o[c] = bb[c];
#pragma unroll 4
        for (int k = 0; k < 40; k++) {
            float a = h[k];
            const float4* w = (const float4*)&Wb[k * 40];
#pragma unroll
            for (int q = 0; q < 10; q++) {
                float4 wv = w[q];
                o[q * 4 + 0] = fmaf(a, wv.x, o[q * 4 + 0]);
                o[q * 4 + 1] = fmaf(a, wv.y, o[q * 4 + 1]);
                o[q * 4 + 2] = fmaf(a, wv.z, o[q * 4 + 2]);
                o[q * 4 + 3] = fmaf(a, wv.w, o[q * 4 + 3]);
            }
        }
        float mx = o[0];
#pragma unroll
        for (int c = 1; c < 40; c++) mx = fmaxf(mx, o[c]);
        float s = 0.f;
#pragma unroll
        for (int c = 0; c < 40; c++) { float e = __expf(o[c] - mx); o[c] = e; s += e; }
        float inv = 1.0f / s;
#pragma unroll
        for (int c = 0; c < 40; c++) As[tid * 41 + c] = o[c] * inv;
    }
    __syncthreads();
    for (int i = tid; i < G2B_ROWS * 40; i += 256) {
        int r = i / 40, c = i - r * 40;
        int row = row0 + r;
        if (row < n) out[(size_t)row * 40 + c] = As[r * 41 + c];
    }
}

// ---------------- launcher --------------------------------------------------
extern "C" void kernel_launch(void* const* d_in, const int* in_sizes, int n_in,
                              void* d_out, int out_size) {
    int i_nodes = 0, i_edges = -1;
    for (int i = 1; i < n_in; i++)
        if (in_sizes[i] > in_sizes[i_nodes]) i_nodes = i;
    for (int i = 0; i < n_in; i++) {
        if (i == i_nodes) continue;
        if (i_edges < 0 || in_sizes[i] > in_sizes[i_edges]) i_edges = i;
    }

    const float* x0  = (const float*)d_in[i_nodes];
    const int2*  ei  = (const int2*)d_in[i_edges];
    int n = in_sizes[i_nodes] / DIM;
    int m = in_sizes[i_edges] / 2;
    int m4 = m >> 1;  // int4 = 2 edges

    const float *W1a = 0, *W1b = 0, *b1a = 0, *b1b = 0;
    const float *W2a = 0, *W2b = 0, *b2a = 0, *b2b = 0;
    for (int i = 0; i < n_in; i++) {
        if (i == i_nodes || i == i_edges) continue;
        int s = in_sizes[i];
        const float* p = (const float*)d_in[i];
        if (s == DIM * DIM)        { if (!W1a) W1a = p; else W1b = p; }
        else if (s == DIM)         { if (!b1a) b1a = p; else b1b = p; }
        else if (s == DIM * NCLS)  W2a = p;
        else if (s == NCLS * NCLS) W2b = p;
        else if (s == NCLS)        { if (!b2a) b2a = p; else b2b = p; }
    }
    float* out = (float*)d_out;

    const int g2b_smem = G2B_SMEM_FLOATS * (int)sizeof(float);
    cudaFuncSetAttribute(gemm1_kernel, cudaFuncAttributeMaxDynamicSharedMemorySize, G1_SMEM_BYTES);
    cudaFuncSetAttribute(gemm2b_kernel, cudaFuncAttributeMaxDynamicSharedMemorySize, g2b_smem);

    void* deg_ptr;
    cudaGetSymbolAddress(&deg_ptr, g_deg);

    int nb = (n + SCB - 1) / SCB;             // 98 for n=100k (<=128 required)
    int eb = (m4 + 1023) / 1024;              // 4 int4 per thread, 256 threads

    // weight pre-conversion (once) + CSR build
    cudaMemsetAsync(deg_ptr, 0, (size_t)n * sizeof(int));
    convert_weights_kernel<<<32, 256>>>(W1a, W1b, W2a);
    hist_kernel<<<eb, 256>>>((const int4*)ei, m4, ei, m);
    scan_kernel<<<nb, 256>>>(n, nb);
    fill_kernel<<<eb, 256>>>((const int4*)ei, m4, ei, m);

    // layer 1 + y1 projection (x1 never materialized)
    agg_kernel<<<((size_t)n * 32 + 255) / 256, 256>>>((const float4*)x0, n);
    gemm1_kernel<<<(n + 63) / 64, 256, G1_SMEM_BYTES>>>(b1a, b1b, n);

    // layer 2: fused aggregate + tiny GEMM + softmax
    gemm2b_kernel<<<(n + G2B_ROWS - 1) / G2B_ROWS, 256, g2b_smem>>>(b2a, W2b, b2b, out, n);
}